// round 9
// baseline (speedup 1.0000x reference)
#include <cuda_runtime.h>
#include <math.h>
#include <cstdint>

#define BB 256
#define TT 256
#define DD 64
#define HH 256
#define G3 768   // 3*H
#define NBLK 128
#define NGRP 16  // (dir, b-tile) groups, 8 blocks each

// ---------------- device scratch (allocation-free) ----------------
__device__ float g_gi0[2ull * TT * BB * G3];
__device__ float g_gi1[2ull * TT * BB * G3];
__device__ float g_y0 [2ull * TT * BB * HH];
__device__ float g_y1 [2ull * TT * BB * HH];
__device__ unsigned g_ctrs[NGRP];   // per-group step counters (zero-init)
__device__ unsigned g_ctre[NGRP];   // per-group exit counters (zero-init)

// ================= mma.sync tf32 helpers (sm_80+, family-agnostic) ========
__device__ __forceinline__ uint32_t f2tf32(float f) {
    uint32_t r;
    asm("cvt.rna.tf32.f32 %0, %1;" : "=r"(r) : "f"(f));
    return r;
}
__device__ __forceinline__ void mma1688(float* d, const uint32_t* a, const uint32_t* b) {
    asm volatile(
        "mma.sync.aligned.m16n8k8.row.col.f32.tf32.tf32.f32 "
        "{%0,%1,%2,%3}, {%4,%5,%6,%7}, {%8,%9}, {%0,%1,%2,%3};"
        : "+f"(d[0]), "+f"(d[1]), "+f"(d[2]), "+f"(d[3])
        : "r"(a[0]), "r"(a[1]), "r"(a[2]), "r"(a[3]), "r"(b[0]), "r"(b[1]));
}

// =================================================================
// gi GEMM via mma.sync tf32 (unchanged from R7/R8 — proven).
// =================================================================
#define KC 32
#define AP 36

template<int KDIM, int MODE>
__global__ __launch_bounds__(256)
void gi_mma_kernel(const float* __restrict__ x,
                   const float* __restrict__ w_ih,   // [2][G3][KDIM]
                   const float* __restrict__ b_ih)   // [2][G3]
{
    __shared__ uint32_t as[128 * AP];
    __shared__ uint32_t wsm[64 * AP];

    const int tid  = threadIdx.x;
    const int wid  = tid >> 5;
    const int lane = tid & 31;
    const int g    = lane >> 2;
    const int tig  = lane & 3;

    const int bx  = blockIdx.x;
    const int t   = bx >> 1;
    const int b0  = (bx & 1) * 128;
    const int n0  = blockIdx.y * 64;
    const int dir = blockIdx.z;

    const int wm = wid >> 1;
    const int wn = wid & 1;

    const float* wdir = w_ih + (size_t)dir * G3 * KDIM;

    float acc[2][4][4];
#pragma unroll
    for (int mf = 0; mf < 2; mf++)
#pragma unroll
        for (int nf = 0; nf < 4; nf++)
#pragma unroll
            for (int q = 0; q < 4; q++) acc[mf][nf][q] = 0.f;

    for (int c = 0; c < KDIM / KC; c++) {
        const int koff = c * KC;

#pragma unroll
        for (int i = 0; i < 4; i++) {
            int idx = tid + 256 * i;
            int row = idx >> 3;
            int kq  = (idx & 7) * 4;
            float4 v;
            if (MODE == 0) {
                v = *(const float4*)(x + ((size_t)(b0 + row) * TT + t) * DD + koff + kq);
            } else {
                int k = koff + kq;
                if (k < HH)
                    v = *(const float4*)(g_y0 + ((size_t)t * BB + b0 + row) * HH + k);
                else
                    v = *(const float4*)(g_y0 + (size_t)TT * BB * HH +
                                         ((size_t)t * BB + b0 + row) * HH + (k - HH));
            }
            uint32_t* p = &as[row * AP + kq];
            p[0] = f2tf32(v.x); p[1] = f2tf32(v.y);
            p[2] = f2tf32(v.z); p[3] = f2tf32(v.w);
        }
#pragma unroll
        for (int i = 0; i < 2; i++) {
            int idx = tid + 256 * i;
            int row = idx >> 3;
            int kq  = (idx & 7) * 4;
            float4 v = *(const float4*)(wdir + (size_t)(n0 + row) * KDIM + koff + kq);
            uint32_t* p = &wsm[row * AP + kq];
            p[0] = f2tf32(v.x); p[1] = f2tf32(v.y);
            p[2] = f2tf32(v.z); p[3] = f2tf32(v.w);
        }
        __syncthreads();

#pragma unroll
        for (int kk = 0; kk < KC; kk += 8) {
            uint32_t afr[2][4], bfr[4][2];
#pragma unroll
            for (int mf = 0; mf < 2; mf++) {
                int base = wm * 32 + mf * 16;
                afr[mf][0] = as[(base + g)     * AP + kk + tig];
                afr[mf][1] = as[(base + g + 8) * AP + kk + tig];
                afr[mf][2] = as[(base + g)     * AP + kk + tig + 4];
                afr[mf][3] = as[(base + g + 8) * AP + kk + tig + 4];
            }
#pragma unroll
            for (int nf = 0; nf < 4; nf++) {
                int nb = wn * 32 + nf * 8;
                bfr[nf][0] = wsm[(nb + g) * AP + kk + tig];
                bfr[nf][1] = wsm[(nb + g) * AP + kk + tig + 4];
            }
#pragma unroll
            for (int mf = 0; mf < 2; mf++)
#pragma unroll
                for (int nf = 0; nf < 4; nf++)
                    mma1688(acc[mf][nf], afr[mf], bfr[nf]);
        }
        __syncthreads();
    }

    float* gout = (MODE == 0) ? g_gi0 : g_gi1;
    const float* bias = b_ih + dir * G3;

#pragma unroll
    for (int mf = 0; mf < 2; mf++) {
#pragma unroll
        for (int rs = 0; rs < 2; rs++) {
            int mloc = wm * 32 + mf * 16 + g + rs * 8;
            int b = b0 + mloc;
            float* orow = gout + (((size_t)dir * TT + t) * BB + b) * G3 + n0;
#pragma unroll
            for (int nf = 0; nf < 4; nf++) {
                int col = wn * 32 + nf * 8 + 2 * tig;
                float2 o;
                o.x = acc[mf][nf][rs * 2 + 0] + bias[n0 + col];
                o.y = acc[mf][nf][rs * 2 + 1] + bias[n0 + col + 1];
                *(float2*)(orow + col) = o;
            }
        }
    }
}

// =================================================================
// Persistent per-layer recurrence kernel (tf32 mma.sync, v2).
// Grid = 128 blocks = 2 dirs x 8 b-tiles(32) x 8 j-tiles(32); 8 warps.
// Warp = (wm: 16 rows) x (wn: 8 j) x 3 gates. r/z gates use h-hi only;
// n gate uses hi+lo (fp32-accurate where it matters).
// Barrier groups: 8 blocks sharing (dir, b-tile).
// smem: wsf 96KB + hs_hi 32.5KB + hs_lo 32.5KB = 161KB.
// =================================================================
#define HSP 260
#define WSF_U2   (3 * 4 * 32 * 32)               // uint2 elements = 12288
#define WSF_BYTES (WSF_U2 * 8)                   // 98304
#define HS_FLOATS (32 * HSP)                     // 8320
#define HS_BYTES  (HS_FLOATS * 4)                // 33280
#define LAYER_SMEM (WSF_BYTES + 2 * HS_BYTES)    // 164864

template<int LAYER>
__global__ __launch_bounds__(256)
void layer_kernel(const float* __restrict__ w_hh,   // [2][G3][H]
                  const float* __restrict__ b_hh)   // [2][G3]
{
    extern __shared__ char smraw[];
    uint2*    wsf   = (uint2*)smraw;
    uint32_t* hs_hi = (uint32_t*)(smraw + WSF_BYTES);
    uint32_t* hs_lo = (uint32_t*)(smraw + WSF_BYTES + HS_BYTES);

    const int bid = blockIdx.x;
    const int dir = bid >> 6;
    const int rr  = bid & 63;
    const int b0  = (rr >> 3) * 32;    // b-tile of 32 rows
    const int j0  = (rr & 7) * 32;     // j-tile of 32 cols
    const int grp = bid >> 3;          // (dir, b-tile) group of 8 blocks

    const int tid  = threadIdx.x;
    const int wid  = tid >> 5;
    const int lane = tid & 31;
    const int g    = lane >> 2;
    const int tig  = lane & 3;
    const int wm   = wid >> 2;      // 0..1: row half (16 rows)
    const int wn   = wid & 3;       // 0..3: j octet within 32-j tile

    const float* gi = LAYER ? g_gi1 : g_gi0;
    float*       y  = LAYER ? g_y1  : g_y0;
    const float* w  = w_hh + (size_t)dir * G3 * HH;
    const float* bh = b_hh + dir * G3;

    // ---- pack weight fragments once ----
    // wsf[g3][ww][kk][lane] = (tf32 W[g3*H + j0 + ww*8 + lane/4][kk*8 + lane%4],
    //                          same row, k + 4)
    for (int e = tid; e < WSF_U2; e += 256) {
        int el = e & 31;
        int kk = (e >> 5) & 31;
        int ww = (e >> 10) & 3;
        int g3 = e >> 12;
        int j  = j0 + ww * 8 + (el >> 2);
        int k0 = kk * 8 + (el & 3);
        const float* wr = w + (size_t)(g3 * HH + j) * HH;
        uint2 bv;
        bv.x = f2tf32(wr[k0]);
        bv.y = f2tf32(wr[k0 + 4]);
        wsf[e] = bv;
    }

    const int jj = wn * 8 + 2 * tig;      // local j in [0,32)
    const int jglob = j0 + jj;            // global hidden index
    float2 bhr = *(const float2*)&bh[jglob];
    float2 bhz = *(const float2*)&bh[HH + jglob];
    float2 bhn = *(const float2*)&bh[2 * HH + jglob];

    __syncthreads();

    volatile unsigned* vc = &g_ctrs[grp];
    const uint2* wsf_w = wsf + (size_t)wn * 1024;   // [g3*4096 + kk*32 + lane]
    const int r0 = wm * 16;                          // warp's local row base

    for (int t = 0; t < TT; t++) {
        const int teff = (dir == 0) ? t : (TT - 1 - t);
        const float* gi_t = gi + ((size_t)(dir * TT + teff) * BB) * G3;
        float*       y_t  = y  + ((size_t)(dir * TT + teff) * BB) * HH;

        // ---- prefetch gi early (resolves under staging + MMA) ----
        float2 gir[2], giz[2], gin[2];
#pragma unroll
        for (int rs = 0; rs < 2; rs++) {
            const int b = b0 + r0 + g + rs * 8;
            const float* girow = gi_t + (size_t)b * G3;
            gir[rs] = *(const float2*)&girow[jglob];
            giz[rs] = *(const float2*)&girow[HH + jglob];
            gin[rs] = *(const float2*)&girow[2 * HH + jglob];
        }

        float acc[3][4];
#pragma unroll
        for (int g3 = 0; g3 < 3; g3++)
#pragma unroll
            for (int q = 0; q < 4; q++) acc[g3][q] = 0.f;

        if (t > 0) {
            const int tprev = (dir == 0) ? (teff - 1) : (teff + 1);
            const float* h_prev = y + ((size_t)(dir * TT + tprev) * BB) * HH;

            // ---- stage 32-row h slice as tf32 hi/lo (8 float4 per thread) ----
#pragma unroll
            for (int it = 0; it < 8; it++) {
                int idx = tid + 256 * it;      // 0..2047
                int kq  = idx & 63;
                int b   = idx >> 6;            // 0..31
                float4 v = *(const float4*)(h_prev + (size_t)(b0 + b) * HH + kq * 4);
                uint4 hi, lo;
                hi.x = f2tf32(v.x); lo.x = f2tf32(v.x - __uint_as_float(hi.x));
                hi.y = f2tf32(v.y); lo.y = f2tf32(v.y - __uint_as_float(hi.y));
                hi.z = f2tf32(v.z); lo.z = f2tf32(v.z - __uint_as_float(hi.z));
                hi.w = f2tf32(v.w); lo.w = f2tf32(v.w - __uint_as_float(hi.w));
                *(uint4*)&hs_hi[b * HSP + kq * 4] = hi;
                *(uint4*)&hs_lo[b * HSP + kq * 4] = lo;
            }
            __syncthreads();

            // ---- tensor k-loop: r/z hi-only, n hi+lo -> 4 MMA per kk ----
#pragma unroll 4
            for (int kk = 0; kk < 32; kk++) {
                int ko = kk * 8;
                uint32_t ahi[4], alo[4];
                ahi[0] = hs_hi[(r0 + g)     * HSP + ko + tig];
                ahi[1] = hs_hi[(r0 + g + 8) * HSP + ko + tig];
                ahi[2] = hs_hi[(r0 + g)     * HSP + ko + tig + 4];
                ahi[3] = hs_hi[(r0 + g + 8) * HSP + ko + tig + 4];
                alo[0] = hs_lo[(r0 + g)     * HSP + ko + tig];
                alo[1] = hs_lo[(r0 + g + 8) * HSP + ko + tig];
                alo[2] = hs_lo[(r0 + g)     * HSP + ko + tig + 4];
                alo[3] = hs_lo[(r0 + g + 8) * HSP + ko + tig + 4];

                uint2 bv0 = wsf_w[0 * 4096 + kk * 32 + lane];
                uint2 bv1 = wsf_w[1 * 4096 + kk * 32 + lane];
                uint2 bv2 = wsf_w[2 * 4096 + kk * 32 + lane];
                uint32_t bf0[2] = {bv0.x, bv0.y};
                uint32_t bf1[2] = {bv1.x, bv1.y};
                uint32_t bf2[2] = {bv2.x, bv2.y};
                mma1688(acc[0], ahi, bf0);
                mma1688(acc[1], ahi, bf1);
                mma1688(acc[2], ahi, bf2);
                mma1688(acc[2], alo, bf2);
            }
        }

        // ---- gate math + store: 2 row-halves x 2 j cols per thread ----
#pragma unroll
        for (int rs = 0; rs < 2; rs++) {
            const int rl = r0 + g + rs * 8;          // local row
            const int b  = b0 + rl;                  // global batch row

            float hp0 = 0.f, hp1 = 0.f;
            if (t > 0) {
                hp0 = __uint_as_float(hs_hi[rl * HSP + jglob]) +
                      __uint_as_float(hs_lo[rl * HSP + jglob]);
                hp1 = __uint_as_float(hs_hi[rl * HSP + jglob + 1]) +
                      __uint_as_float(hs_lo[rl * HSP + jglob + 1]);
            }

            float rv0 = 1.f / (1.f + expf(-(gir[rs].x + acc[0][rs * 2 + 0] + bhr.x)));
            float rv1 = 1.f / (1.f + expf(-(gir[rs].y + acc[0][rs * 2 + 1] + bhr.y)));
            float zv0 = 1.f / (1.f + expf(-(giz[rs].x + acc[1][rs * 2 + 0] + bhz.x)));
            float zv1 = 1.f / (1.f + expf(-(giz[rs].y + acc[1][rs * 2 + 1] + bhz.y)));
            float nv0 = tanhf(gin[rs].x + rv0 * (acc[2][rs * 2 + 0] + bhn.x));
            float nv1 = tanhf(gin[rs].y + rv1 * (acc[2][rs * 2 + 1] + bhn.y));

            float2 o;
            o.x = (1.f - zv0) * nv0 + zv0 * hp0;
            o.y = (1.f - zv1) * nv1 + zv1 * hp1;
            *(float2*)(y_t + (size_t)b * HH + jglob) = o;
        }

        // ---- group barrier (8 blocks sharing (dir, b-tile)) ----
        if (t < TT - 1) {
            __syncthreads();
            if (tid == 0) {
                __threadfence();
                atomicAdd(&g_ctrs[grp], 1);
                unsigned target = (unsigned)(t + 1) * 8;
                while (*vc < target) { }
                __threadfence();
            }
            __syncthreads();
        }
    }

    // deadlock-safe per-group counter reset for graph replay
    __syncthreads();
    if (tid == 0) {
        atomicAdd(&g_ctre[grp], 1);
        if ((bid & 7) == 0) {
            volatile unsigned* ve = &g_ctre[grp];
            while (*ve < 8) { }
            *(volatile unsigned*)&g_ctrs[grp] = 0;
            *(volatile unsigned*)&g_ctre[grp] = 0;
            __threadfence();
        }
    }
}

// =================================================================
// Gather: out[b][0:H] = y1_fwd[T-1][b], out[b][H:2H] = y1_bwd[0][b]
// =================================================================
__global__ void gather_kernel(float* __restrict__ out)
{
    int idx = blockIdx.x * blockDim.x + threadIdx.x;
    int b = idx >> 9;
    int j = idx & 511;
    float v;
    if (j < HH)
        v = g_y1[(((size_t)0 * TT + (TT - 1)) * BB + b) * HH + j];
    else
        v = g_y1[(((size_t)1 * TT + 0) * BB + b) * HH + (j - HH)];
    out[idx] = v;
}

// =================================================================
extern "C" void kernel_launch(void* const* d_in, const int* in_sizes, int n_in,
                              void* d_out, int out_size)
{
    const float* x     = (const float*)d_in[0];
    const float* w_ih0 = (const float*)d_in[1];
    const float* w_hh0 = (const float*)d_in[2];
    const float* b_ih0 = (const float*)d_in[3];
    const float* b_hh0 = (const float*)d_in[4];
    const float* w_ih1 = (const float*)d_in[5];
    const float* w_hh1 = (const float*)d_in[6];
    const float* b_ih1 = (const float*)d_in[7];
    const float* b_hh1 = (const float*)d_in[8];
    float* out = (float*)d_out;

    cudaFuncSetAttribute(layer_kernel<0>,
                         cudaFuncAttributeMaxDynamicSharedMemorySize, LAYER_SMEM);
    cudaFuncSetAttribute(layer_kernel<1>,
                         cudaFuncAttributeMaxDynamicSharedMemorySize, LAYER_SMEM);

    dim3 mma_grid(512, 12, 2);   // m-tiles(65536/128), n-tiles(768/64), dirs

    gi_mma_kernel<DD, 0><<<mma_grid, 256>>>(x, w_ih0, b_ih0);
    layer_kernel<0><<<NBLK, 256, LAYER_SMEM>>>(w_hh0, b_hh0);
    gi_mma_kernel<2 * HH, 1><<<mma_grid, 256>>>(nullptr, w_ih1, b_ih1);
    layer_kernel<1><<<NBLK, 256, LAYER_SMEM>>>(w_hh1, b_hh1);
    gather_kernel<<<512, 256>>>(out);
}

// round 10
// speedup vs baseline: 1.0122x; 1.0122x over previous
#include <cuda_runtime.h>
#include <math.h>
#include <cstdint>

#define BB 256
#define TT 256
#define DD 64
#define HH 256
#define G3 768   // 3*H
#define NBLK 128
#define NGRP 8   // (dir, b-tile64) groups, 16 blocks each

// ---------------- device scratch (allocation-free) ----------------
__device__ float g_gi0[2ull * TT * BB * G3];
__device__ float g_gi1[2ull * TT * BB * G3];
__device__ float g_y0 [2ull * TT * BB * HH];
__device__ float g_y1 [2ull * TT * BB * HH];
__device__ unsigned g_ctrs[NGRP];   // per-group step counters (zero-init)
__device__ unsigned g_ctre[NGRP];   // per-group exit counters (zero-init)

// ================= mma.sync tf32 helpers (sm_80+, family-agnostic) ========
__device__ __forceinline__ uint32_t f2tf32(float f) {
    uint32_t r;
    asm("cvt.rna.tf32.f32 %0, %1;" : "=r"(r) : "f"(f));
    return r;
}
__device__ __forceinline__ void mma1688(float* d, const uint32_t* a, const uint32_t* b) {
    asm volatile(
        "mma.sync.aligned.m16n8k8.row.col.f32.tf32.tf32.f32 "
        "{%0,%1,%2,%3}, {%4,%5,%6,%7}, {%8,%9}, {%0,%1,%2,%3};"
        : "+f"(d[0]), "+f"(d[1]), "+f"(d[2]), "+f"(d[3])
        : "r"(a[0]), "r"(a[1]), "r"(a[2]), "r"(a[3]), "r"(b[0]), "r"(b[1]));
}
// release arrive / acquire poll (no CCTL.IVALL, unlike __threadfence)
__device__ __forceinline__ void red_add_release(unsigned* p) {
    asm volatile("red.release.gpu.global.add.u32 [%0], 1;" :: "l"(p) : "memory");
}
__device__ __forceinline__ unsigned ld_acquire(unsigned* p) {
    unsigned v;
    asm volatile("ld.acquire.gpu.global.u32 %0, [%1];" : "=r"(v) : "l"(p) : "memory");
    return v;
}

// =================================================================
// gi GEMM via mma.sync tf32 (unchanged — proven).
// =================================================================
#define KC 32
#define AP 36

template<int KDIM, int MODE>
__global__ __launch_bounds__(256)
void gi_mma_kernel(const float* __restrict__ x,
                   const float* __restrict__ w_ih,   // [2][G3][KDIM]
                   const float* __restrict__ b_ih)   // [2][G3]
{
    __shared__ uint32_t as[128 * AP];
    __shared__ uint32_t wsm[64 * AP];

    const int tid  = threadIdx.x;
    const int wid  = tid >> 5;
    const int lane = tid & 31;
    const int g    = lane >> 2;
    const int tig  = lane & 3;

    const int bx  = blockIdx.x;
    const int t   = bx >> 1;
    const int b0  = (bx & 1) * 128;
    const int n0  = blockIdx.y * 64;
    const int dir = blockIdx.z;

    const int wm = wid >> 1;
    const int wn = wid & 1;

    const float* wdir = w_ih + (size_t)dir * G3 * KDIM;

    float acc[2][4][4];
#pragma unroll
    for (int mf = 0; mf < 2; mf++)
#pragma unroll
        for (int nf = 0; nf < 4; nf++)
#pragma unroll
            for (int q = 0; q < 4; q++) acc[mf][nf][q] = 0.f;

    for (int c = 0; c < KDIM / KC; c++) {
        const int koff = c * KC;

#pragma unroll
        for (int i = 0; i < 4; i++) {
            int idx = tid + 256 * i;
            int row = idx >> 3;
            int kq  = (idx & 7) * 4;
            float4 v;
            if (MODE == 0) {
                v = *(const float4*)(x + ((size_t)(b0 + row) * TT + t) * DD + koff + kq);
            } else {
                int k = koff + kq;
                if (k < HH)
                    v = *(const float4*)(g_y0 + ((size_t)t * BB + b0 + row) * HH + k);
                else
                    v = *(const float4*)(g_y0 + (size_t)TT * BB * HH +
                                         ((size_t)t * BB + b0 + row) * HH + (k - HH));
            }
            uint32_t* p = &as[row * AP + kq];
            p[0] = f2tf32(v.x); p[1] = f2tf32(v.y);
            p[2] = f2tf32(v.z); p[3] = f2tf32(v.w);
        }
#pragma unroll
        for (int i = 0; i < 2; i++) {
            int idx = tid + 256 * i;
            int row = idx >> 3;
            int kq  = (idx & 7) * 4;
            float4 v = *(const float4*)(wdir + (size_t)(n0 + row) * KDIM + koff + kq);
            uint32_t* p = &wsm[row * AP + kq];
            p[0] = f2tf32(v.x); p[1] = f2tf32(v.y);
            p[2] = f2tf32(v.z); p[3] = f2tf32(v.w);
        }
        __syncthreads();

#pragma unroll
        for (int kk = 0; kk < KC; kk += 8) {
            uint32_t afr[2][4], bfr[4][2];
#pragma unroll
            for (int mf = 0; mf < 2; mf++) {
                int base = wm * 32 + mf * 16;
                afr[mf][0] = as[(base + g)     * AP + kk + tig];
                afr[mf][1] = as[(base + g + 8) * AP + kk + tig];
                afr[mf][2] = as[(base + g)     * AP + kk + tig + 4];
                afr[mf][3] = as[(base + g + 8) * AP + kk + tig + 4];
            }
#pragma unroll
            for (int nf = 0; nf < 4; nf++) {
                int nb = wn * 32 + nf * 8;
                bfr[nf][0] = wsm[(nb + g) * AP + kk + tig];
                bfr[nf][1] = wsm[(nb + g) * AP + kk + tig + 4];
            }
#pragma unroll
            for (int mf = 0; mf < 2; mf++)
#pragma unroll
                for (int nf = 0; nf < 4; nf++)
                    mma1688(acc[mf][nf], afr[mf], bfr[nf]);
        }
        __syncthreads();
    }

    float* gout = (MODE == 0) ? g_gi0 : g_gi1;
    const float* bias = b_ih + dir * G3;

#pragma unroll
    for (int mf = 0; mf < 2; mf++) {
#pragma unroll
        for (int rs = 0; rs < 2; rs++) {
            int mloc = wm * 32 + mf * 16 + g + rs * 8;
            int b = b0 + mloc;
            float* orow = gout + (((size_t)dir * TT + t) * BB + b) * G3 + n0;
#pragma unroll
            for (int nf = 0; nf < 4; nf++) {
                int col = wn * 32 + nf * 8 + 2 * tig;
                float2 o;
                o.x = acc[mf][nf][rs * 2 + 0] + bias[n0 + col];
                o.y = acc[mf][nf][rs * 2 + 1] + bias[n0 + col + 1];
                *(float2*)(orow + col) = o;
            }
        }
    }
}

// =================================================================
// Persistent per-layer recurrence (R8 structure + light barrier + 4MMA).
// Grid = 128 blocks (dir | b-tile(64) | j-tile(16)), 256 thr = 8 warps.
// Warp = (wm: 16 b-rows) x (wn: 8 j) x 3 gates.
// r/z gates: h-hi only. n gate: hi+lo (fp32-accurate).
// Barrier: __syncthreads -> red.release arrive -> ld.acquire spin
// (addresses are read-once per layer, so no L1-invalidate is needed).
// =================================================================
#define HSP 260
#define WSF_BYTES (3 * 2 * 32 * 32 * 8)         // 49152
#define HS_BYTES  (64 * HSP * 4)                 // 66560
#define LAYER_SMEM (WSF_BYTES + 2 * HS_BYTES)    // 182272

template<int LAYER>
__global__ __launch_bounds__(256)
void layer_kernel(const float* __restrict__ w_hh,   // [2][G3][H]
                  const float* __restrict__ b_hh)   // [2][G3]
{
    extern __shared__ char smraw[];
    uint2*    wsf   = (uint2*)smraw;
    uint32_t* hs_hi = (uint32_t*)(smraw + WSF_BYTES);
    uint32_t* hs_lo = (uint32_t*)(smraw + WSF_BYTES + HS_BYTES);

    const int bid = blockIdx.x;
    const int dir = bid >> 6;
    const int rr  = bid & 63;
    const int j0  = (rr & 15) * 16;
    const int b0  = (rr >> 4) * 64;
    const int grp = bid >> 4;          // (dir, b-tile) group of 16 blocks

    const int tid  = threadIdx.x;
    const int wid  = tid >> 5;
    const int lane = tid & 31;
    const int g    = lane >> 2;
    const int tig  = lane & 3;
    const int wm   = wid >> 1;      // 0..3: m sub-tile (16 rows)
    const int wn   = wid & 1;       // 0..1: j half (8 cols)

    const float* gi = LAYER ? g_gi1 : g_gi0;
    float*       y  = LAYER ? g_y1  : g_y0;
    const float* w  = w_hh + (size_t)dir * G3 * HH;
    const float* bh = b_hh + dir * G3;

    // ---- pack weight fragments once ----
    for (int e = tid; e < 3 * 2 * 32 * 32; e += 256) {
        int el = e & 31;
        int kk = (e >> 5) & 31;
        int ww = (e >> 10) & 1;
        int g3 = e >> 11;
        int j  = j0 + ww * 8 + (el >> 2);
        int k0 = kk * 8 + (el & 3);
        const float* wr = w + (size_t)(g3 * HH + j) * HH;
        uint2 bv;
        bv.x = f2tf32(wr[k0]);
        bv.y = f2tf32(wr[k0 + 4]);
        wsf[e] = bv;
    }

    const int jj = wn * 8 + 2 * tig;
    const int jglob = j0 + jj;
    float2 bhr = *(const float2*)&bh[jglob];
    float2 bhz = *(const float2*)&bh[HH + jglob];
    float2 bhn = *(const float2*)&bh[2 * HH + jglob];

    __syncthreads();

    const uint2* wsf_w = wsf + (size_t)wn * 1024;
    const int r0 = wm * 16;

    for (int t = 0; t < TT; t++) {
        const int teff = (dir == 0) ? t : (TT - 1 - t);
        const float* gi_t = gi + ((size_t)(dir * TT + teff) * BB) * G3;
        float*       y_t  = y  + ((size_t)(dir * TT + teff) * BB) * HH;

        // ---- prefetch gi early ----
        float2 gir[2], giz[2], gin[2];
#pragma unroll
        for (int rs = 0; rs < 2; rs++) {
            const int b = b0 + r0 + g + rs * 8;
            const float* girow = gi_t + (size_t)b * G3;
            gir[rs] = *(const float2*)&girow[jglob];
            giz[rs] = *(const float2*)&girow[HH + jglob];
            gin[rs] = *(const float2*)&girow[2 * HH + jglob];
        }

        float acc[3][4];
#pragma unroll
        for (int g3 = 0; g3 < 3; g3++)
#pragma unroll
            for (int q = 0; q < 4; q++) acc[g3][q] = 0.f;

        if (t > 0) {
            const int tprev = (dir == 0) ? (teff - 1) : (teff + 1);
            const float* h_prev = y + ((size_t)(dir * TT + tprev) * BB) * HH;

            // ---- stage h slice as tf32 hi/lo ----
#pragma unroll
            for (int it = 0; it < 16; it++) {
                int idx = tid + 256 * it;      // 0..4095
                int kq  = idx & 63;
                int b   = idx >> 6;
                float4 v = *(const float4*)(h_prev + (size_t)(b0 + b) * HH + kq * 4);
                uint4 hi, lo;
                hi.x = f2tf32(v.x); lo.x = f2tf32(v.x - __uint_as_float(hi.x));
                hi.y = f2tf32(v.y); lo.y = f2tf32(v.y - __uint_as_float(hi.y));
                hi.z = f2tf32(v.z); lo.z = f2tf32(v.z - __uint_as_float(hi.z));
                hi.w = f2tf32(v.w); lo.w = f2tf32(v.w - __uint_as_float(hi.w));
                *(uint4*)&hs_hi[b * HSP + kq * 4] = hi;
                *(uint4*)&hs_lo[b * HSP + kq * 4] = lo;
            }
            __syncthreads();

            // ---- tensor k-loop: r/z hi-only, n hi+lo -> 4 MMA per kk ----
#pragma unroll 4
            for (int kk = 0; kk < 32; kk++) {
                int ko = kk * 8;
                uint32_t ahi[4], alo[4];
                ahi[0] = hs_hi[(r0 + g)     * HSP + ko + tig];
                ahi[1] = hs_hi[(r0 + g + 8) * HSP + ko + tig];
                ahi[2] = hs_hi[(r0 + g)     * HSP + ko + tig + 4];
                ahi[3] = hs_hi[(r0 + g + 8) * HSP + ko + tig + 4];
                alo[0] = hs_lo[(r0 + g)     * HSP + ko + tig];
                alo[1] = hs_lo[(r0 + g + 8) * HSP + ko + tig];
                alo[2] = hs_lo[(r0 + g)     * HSP + ko + tig + 4];
                alo[3] = hs_lo[(r0 + g + 8) * HSP + ko + tig + 4];
#pragma unroll
                for (int g3 = 0; g3 < 3; g3++) {
                    uint2 bv = wsf_w[g3 * 2048 + kk * 32 + lane];
                    uint32_t bf[2] = {bv.x, bv.y};
                    mma1688(acc[g3], ahi, bf);
                    if (g3 == 2) mma1688(acc[g3], alo, bf);
                }
            }
        }

        // ---- gate math + store ----
#pragma unroll
        for (int rs = 0; rs < 2; rs++) {
            const int rl = r0 + g + rs * 8;
            const int b  = b0 + rl;

            float hp0 = 0.f, hp1 = 0.f;
            if (t > 0) {
                hp0 = __uint_as_float(hs_hi[rl * HSP + jglob]) +
                      __uint_as_float(hs_lo[rl * HSP + jglob]);
                hp1 = __uint_as_float(hs_hi[rl * HSP + jglob + 1]) +
                      __uint_as_float(hs_lo[rl * HSP + jglob + 1]);
            }

            float rv0 = 1.f / (1.f + expf(-(gir[rs].x + acc[0][rs * 2 + 0] + bhr.x)));
            float rv1 = 1.f / (1.f + expf(-(gir[rs].y + acc[0][rs * 2 + 1] + bhr.y)));
            float zv0 = 1.f / (1.f + expf(-(giz[rs].x + acc[1][rs * 2 + 0] + bhz.x)));
            float zv1 = 1.f / (1.f + expf(-(giz[rs].y + acc[1][rs * 2 + 1] + bhz.y)));
            float nv0 = tanhf(gin[rs].x + rv0 * (acc[2][rs * 2 + 0] + bhn.x));
            float nv1 = tanhf(gin[rs].y + rv1 * (acc[2][rs * 2 + 1] + bhn.y));

            float2 o;
            o.x = (1.f - zv0) * nv0 + zv0 * hp0;
            o.y = (1.f - zv1) * nv1 + zv1 * hp1;
            *(float2*)(y_t + (size_t)b * HH + jglob) = o;
        }

        // ---- group barrier: release arrive + acquire spin ----
        if (t < TT - 1) {
            __syncthreads();
            if (tid == 0) {
                red_add_release(&g_ctrs[grp]);
                unsigned target = (unsigned)(t + 1) * 16;
                while (ld_acquire(&g_ctrs[grp]) < target) { }
            }
            __syncthreads();
        }
    }

    // deadlock-safe per-group counter reset for graph replay
    __syncthreads();
    if (tid == 0) {
        red_add_release(&g_ctre[grp]);
        if ((bid & 15) == 0) {
            while (ld_acquire(&g_ctre[grp]) < 16) { }
            *(volatile unsigned*)&g_ctrs[grp] = 0;
            *(volatile unsigned*)&g_ctre[grp] = 0;
            __threadfence();
        }
    }
}

// =================================================================
// Gather: out[b][0:H] = y1_fwd[T-1][b], out[b][H:2H] = y1_bwd[0][b]
// =================================================================
__global__ void gather_kernel(float* __restrict__ out)
{
    int idx = blockIdx.x * blockDim.x + threadIdx.x;
    int b = idx >> 9;
    int j = idx & 511;
    float v;
    if (j < HH)
        v = g_y1[(((size_t)0 * TT + (TT - 1)) * BB + b) * HH + j];
    else
        v = g_y1[(((size_t)1 * TT + 0) * BB + b) * HH + (j - HH)];
    out[idx] = v;
}

// =================================================================
extern "C" void kernel_launch(void* const* d_in, const int* in_sizes, int n_in,
                              void* d_out, int out_size)
{
    const float* x     = (const float*)d_in[0];
    const float* w_ih0 = (const float*)d_in[1];
    const float* w_hh0 = (const float*)d_in[2];
    const float* b_ih0 = (const float*)d_in[3];
    const float* b_hh0 = (const float*)d_in[4];
    const float* w_ih1 = (const float*)d_in[5];
    const float* w_hh1 = (const float*)d_in[6];
    const float* b_ih1 = (const float*)d_in[7];
    const float* b_hh1 = (const float*)d_in[8];
    float* out = (float*)d_out;

    cudaFuncSetAttribute(layer_kernel<0>,
                         cudaFuncAttributeMaxDynamicSharedMemorySize, LAYER_SMEM);
    cudaFuncSetAttribute(layer_kernel<1>,
                         cudaFuncAttributeMaxDynamicSharedMemorySize, LAYER_SMEM);

    dim3 mma_grid(512, 12, 2);   // m-tiles(65536/128), n-tiles(768/64), dirs

    gi_mma_kernel<DD, 0><<<mma_grid, 256>>>(x, w_ih0, b_ih0);
    layer_kernel<0><<<NBLK, 256, LAYER_SMEM>>>(w_hh0, b_hh0);
    gi_mma_kernel<2 * HH, 1><<<mma_grid, 256>>>(nullptr, w_ih1, b_ih1);
    layer_kernel<1><<<NBLK, 256, LAYER_SMEM>>>(w_hh1, b_hh1);
    gather_kernel<<<512, 256>>>(out);
}